// round 1
// baseline (speedup 1.0000x reference)
#include <cuda_runtime.h>
#include <math.h>

#define N_NODES 100000
#define N_EDGES 3200000
#define NBLK_N 391            // ceil(100000/256)
#define NBLK_E 12500          // 3200000/256

// ---------------- static device scratch (allocation-free) ----------------
// float pool
#define OFF_H0 0
#define OFF_X1 300000
#define OFF_X2 1100000
#define OFF_X3 2700000
#define OFF_X4 5900000
#define OFF_H5 12300000
#define OFF_H6 15500000
#define OFF_H7 17100000
#define FBUF_SZ 17900000
static __device__ float g_fbuf[FBUF_SZ];

// int pool
#define OFF_DEG 0
#define OFF_ROW 100000
#define OFF_CUR 200000
#define OFF_PART 300000
#define OFF_SRCS 300512
#define IBUF_SZ 3500512
static __device__ int g_ibuf[IBUF_SZ];

// normalization stats (ordered-uint encoding for max/min)
static __device__ unsigned g_maxx, g_minx, g_maxy, g_miny, g_maxrx, g_maxry, g_maxa;
static __device__ float g_sumx, g_sumy;

// ---------------- helpers ----------------
__device__ __forceinline__ unsigned f2o(float f) {
    unsigned u = __float_as_uint(f);
    return (u & 0x80000000u) ? ~u : (u | 0x80000000u);
}
__device__ __forceinline__ float o2f(unsigned u) {
    return (u & 0x80000000u) ? __uint_as_float(u & 0x7FFFFFFFu) : __uint_as_float(~u);
}

__device__ __forceinline__ float blockSum(float v, float* s) {
    int t = threadIdx.x;
    s[t] = v; __syncthreads();
    for (int o = 128; o > 0; o >>= 1) { if (t < o) s[t] += s[t + o]; __syncthreads(); }
    float r = s[0]; __syncthreads();
    return r;
}
__device__ __forceinline__ float blockMax(float v, float* s) {
    int t = threadIdx.x;
    s[t] = v; __syncthreads();
    for (int o = 128; o > 0; o >>= 1) { if (t < o) s[t] = fmaxf(s[t], s[t + o]); __syncthreads(); }
    float r = s[0]; __syncthreads();
    return r;
}
__device__ __forceinline__ float blockMin(float v, float* s) {
    int t = threadIdx.x;
    s[t] = v; __syncthreads();
    for (int o = 128; o > 0; o >>= 1) { if (t < o) s[t] = fminf(s[t], s[t + o]); __syncthreads(); }
    float r = s[0]; __syncthreads();
    return r;
}

// ---------------- setup kernels ----------------
__global__ void k_init_stats() {
    g_maxx = 0u; g_maxy = 0u; g_maxrx = 0u; g_maxry = 0u; g_maxa = 0u;
    g_minx = 0xFFFFFFFFu; g_miny = 0xFFFFFFFFu;
    g_sumx = 0.f; g_sumy = 0.f;
}

__global__ void k_zero_deg() {
    int i = blockIdx.x * blockDim.x + threadIdx.x;
    if (i < N_NODES) g_ibuf[OFF_DEG + i] = 0;
}

__global__ void __launch_bounds__(256) k_stats(const float* __restrict__ x) {
    __shared__ float s[256];
    int n = blockIdx.x * 256 + threadIdx.x;
    float X = -3.402823466e38f, Y = -3.402823466e38f, A = -3.402823466e38f;
    float Xm = 3.402823466e38f, Ym = 3.402823466e38f;
    float sx = 0.f, sy = 0.f, RX = -3.402823466e38f, RY = -3.402823466e38f;
    const float th = (float)(M_PI / 2.0);
    const float c = cosf(th), sn = sinf(th);
    if (n < N_NODES) {
        float px = x[n * 3 + 0], py = x[n * 3 + 1], pa = x[n * 3 + 2];
        X = px; Xm = px; Y = py; Ym = py; A = pa;
        sx = px; sy = py;
        RX = c * px - sn * py;
        RY = sn * px + c * py;
    }
    float bs;
    bs = blockMax(X, s);  if (threadIdx.x == 0) atomicMax(&g_maxx, f2o(bs));
    bs = blockMin(Xm, s); if (threadIdx.x == 0) atomicMin(&g_minx, f2o(bs));
    bs = blockMax(Y, s);  if (threadIdx.x == 0) atomicMax(&g_maxy, f2o(bs));
    bs = blockMin(Ym, s); if (threadIdx.x == 0) atomicMin(&g_miny, f2o(bs));
    bs = blockMax(RX, s); if (threadIdx.x == 0) atomicMax(&g_maxrx, f2o(bs));
    bs = blockMax(RY, s); if (threadIdx.x == 0) atomicMax(&g_maxry, f2o(bs));
    bs = blockMax(A, s);  if (threadIdx.x == 0) atomicMax(&g_maxa, f2o(bs));
    bs = blockSum(sx, s); if (threadIdx.x == 0) atomicAdd(&g_sumx, bs);
    bs = blockSum(sy, s); if (threadIdx.x == 0) atomicAdd(&g_sumy, bs);
}

__global__ void __launch_bounds__(256) k_normalize(const float* __restrict__ x, float* __restrict__ h0) {
    int n = blockIdx.x * 256 + threadIdx.x;
    if (n >= N_NODES) return;
    float maxx = o2f(g_maxx), minx = o2f(g_minx);
    float maxy = o2f(g_maxy), miny = o2f(g_miny);
    float maxa = o2f(g_maxa);
    float meanx = g_sumx / (float)N_NODES, meany = g_sumy / (float)N_NODES;
    bool cond = (maxy - miny) > (maxx - minx);
    const float th = (float)(M_PI / 2.0);
    const float c = cosf(th), sn = sinf(th);
    float px = x[n * 3 + 0], py = x[n * 3 + 1], pa = x[n * 3 + 2];
    float cx, cy, mnx, mny, mxx, mxy;
    if (cond) {
        cx = c * px - sn * py;
        cy = sn * px + c * py;
        mnx = c * meanx - sn * meany;
        mny = sn * meanx + c * meany;
        mxx = o2f(g_maxrx);
        mxy = o2f(g_maxry);
    } else {
        cx = px; cy = py; mnx = meanx; mny = meany; mxx = maxx; mxy = maxy;
    }
    h0[n * 3 + 0] = (cx - mnx) / mxx;
    h0[n * 3 + 1] = (cy - mny) / mxy;
    h0[n * 3 + 2] = pa / maxa;
}

// ---------------- CSR build ----------------
__global__ void k_count(const int* __restrict__ dst) {
    int e = blockIdx.x * blockDim.x + threadIdx.x;
    if (e < N_EDGES) atomicAdd(&g_ibuf[OFF_DEG + dst[e]], 1);
}

__global__ void __launch_bounds__(256) k_scan1() {
    __shared__ int s[256];
    int t = threadIdx.x;
    int i = blockIdx.x * 256 + t;
    s[t] = (i < N_NODES) ? g_ibuf[OFF_DEG + i] : 0;
    __syncthreads();
    for (int o = 128; o > 0; o >>= 1) { if (t < o) s[t] += s[t + o]; __syncthreads(); }
    if (t == 0) g_ibuf[OFF_PART + blockIdx.x] = s[0];
}

__global__ void k_scan2() {
    int run = 0;
    for (int b = 0; b < NBLK_N; b++) {
        int v = g_ibuf[OFF_PART + b];
        g_ibuf[OFF_PART + b] = run;
        run += v;
    }
}

__global__ void __launch_bounds__(256) k_scan3() {
    __shared__ int s[256];
    int t = threadIdx.x;
    int i = blockIdx.x * 256 + t;
    int v = (i < N_NODES) ? g_ibuf[OFF_DEG + i] : 0;
    s[t] = v; __syncthreads();
    for (int o = 1; o < 256; o <<= 1) {
        int a = (t >= o) ? s[t - o] : 0;
        __syncthreads();
        s[t] += a;
        __syncthreads();
    }
    if (i < N_NODES) {
        int ex = g_ibuf[OFF_PART + blockIdx.x] + s[t] - v;
        g_ibuf[OFF_ROW + i] = ex;
        g_ibuf[OFF_CUR + i] = ex;
    }
}

__global__ void k_scatter(const int* __restrict__ src, const int* __restrict__ dst) {
    int e = blockIdx.x * blockDim.x + threadIdx.x;
    if (e < N_EDGES) {
        int pos = atomicAdd(&g_ibuf[OFF_CUR + dst[e]], 1);
        g_ibuf[OFF_SRCS + pos] = src[e];
    }
}

// ---------------- fused SAGE layer ----------------
template <int FI, int FO, bool RES>
__global__ void __launch_bounds__(256) k_sage(const float* __restrict__ xin,
                                              const float* __restrict__ res,
                                              float* __restrict__ xout,
                                              const float* __restrict__ wl,
                                              const float* __restrict__ bl,
                                              const float* __restrict__ wr) {
    constexpr int NB = 256 / FI;      // nodes per block (phase1 = single full pass)
    __shared__ float s_mean[NB * FI];
    __shared__ float s_wl[FI * FO];
    __shared__ float s_wr[FI * FO];
    __shared__ float s_bl[FO];
    int t = threadIdx.x;
    for (int i = t; i < FI * FO; i += 256) { s_wl[i] = wl[i]; s_wr[i] = wr[i]; }
    if (t < FO) s_bl[t] = bl[t];

    int nbase = blockIdx.x * NB;

    // phase 1: mean aggregation via CSR gather (register accumulation)
    int nl = t / FI, fi = t % FI;
    if (nl < NB) {
        int n = nbase + nl;
        float acc = 0.f;
        if (n < N_NODES) {
            int start = g_ibuf[OFF_ROW + n];
            int dg = g_ibuf[OFF_DEG + n];
            const int* sp = &g_ibuf[OFF_SRCS + start];
            float a0 = 0.f, a1 = 0.f, a2 = 0.f, a3 = 0.f;
            int e = 0;
            for (; e + 4 <= dg; e += 4) {
                int s0 = sp[e], s1 = sp[e + 1], s2 = sp[e + 2], s3 = sp[e + 3];
                a0 += xin[s0 * FI + fi];
                a1 += xin[s1 * FI + fi];
                a2 += xin[s2 * FI + fi];
                a3 += xin[s3 * FI + fi];
            }
            for (; e < dg; e++) a0 += xin[sp[e] * FI + fi];
            acc = (a0 + a1) + (a2 + a3);
            acc *= 1.0f / (float)(dg > 0 ? dg : 1);
        }
        s_mean[nl * FI + fi] = acc;
    }
    __syncthreads();

    // phase 2: out = tanh(mean@wl + bl + x@wr) [+ res]
    constexpr int NP2 = 256 / FO;
    for (int p = 0; p < NB; p += NP2) {
        int nl2 = p + t / FO, fo = t % FO;
        if (nl2 < NB) {
            int n = nbase + nl2;
            if (n < N_NODES) {
                float v = s_bl[fo];
#pragma unroll
                for (int i = 0; i < FI; i++) {
                    v += s_mean[nl2 * FI + i] * s_wl[i * FO + fo];
                    v += xin[n * FI + i] * s_wr[i * FO + fo];
                }
                v = tanhf(v);
                if (RES) v += res[n * FO + fo];
                xout[n * FO + fo] = v;
            }
        }
    }
}

// ---------------- MLP head + softmax ----------------
__global__ void __launch_bounds__(256) k_mlp(const float* __restrict__ h,
                                             const float* __restrict__ w1, const float* __restrict__ b1,
                                             const float* __restrict__ w2, const float* __restrict__ b2,
                                             const float* __restrict__ w3, const float* __restrict__ b3,
                                             float* __restrict__ out) {
    __shared__ float s1[8 * 32], sb1[32], s2[32 * 16], sb2[16], s3[16 * 2], sb3[2];
    int t = threadIdx.x;
    for (int i = t; i < 256; i += 256) s1[i] = w1[i];
    for (int i = t; i < 512; i += 256) s2[i] = w2[i];
    if (t < 32) { sb1[t] = b1[t]; s3[t] = w3[t]; }
    if (t < 16) sb2[t] = b2[t];
    if (t < 2) sb3[t] = b3[t];
    __syncthreads();
    int n = blockIdx.x * 256 + t;
    if (n >= N_NODES) return;
    float in8[8];
#pragma unroll
    for (int i = 0; i < 8; i++) in8[i] = h[n * 8 + i];
    float a[32];
#pragma unroll
    for (int j = 0; j < 32; j++) {
        float v = sb1[j];
#pragma unroll
        for (int i = 0; i < 8; i++) v += in8[i] * s1[i * 32 + j];
        a[j] = tanhf(v);
    }
    float bb[16];
#pragma unroll
    for (int j = 0; j < 16; j++) {
        float v = sb2[j];
#pragma unroll
        for (int i = 0; i < 32; i++) v += a[i] * s2[i * 16 + j];
        bb[j] = tanhf(v);
    }
    float c0 = sb3[0], c1 = sb3[1];
#pragma unroll
    for (int i = 0; i < 16; i++) { c0 += bb[i] * s3[i * 2 + 0]; c1 += bb[i] * s3[i * 2 + 1]; }
    float m = fmaxf(c0, c1);
    float e0 = expf(c0 - m), e1 = expf(c1 - m);
    float inv = 1.f / (e0 + e1);
    out[n * 2 + 0] = e0 * inv;
    out[n * 2 + 1] = e1 * inv;
}

// ---------------- launch ----------------
extern "C" void kernel_launch(void* const* d_in, const int* in_sizes, int n_in,
                              void* d_out, int out_size) {
    const float* x = (const float*)d_in[0];
    const int* ei = (const int*)d_in[1];
    const int* src = ei;
    const int* dst = ei + N_EDGES;

    // conv weights: for each of 7 convs: wl, bl, wr starting at index 2
    const float* cw[7][3];
    for (int l = 0; l < 7; l++) {
        cw[l][0] = (const float*)d_in[2 + 3 * l + 0];
        cw[l][1] = (const float*)d_in[2 + 3 * l + 1];
        cw[l][2] = (const float*)d_in[2 + 3 * l + 2];
    }
    const float* lin1_w = (const float*)d_in[23];
    const float* lin1_b = (const float*)d_in[24];
    const float* lin2_w = (const float*)d_in[25];
    const float* lin2_b = (const float*)d_in[26];
    const float* lin3_w = (const float*)d_in[27];
    const float* lin3_b = (const float*)d_in[28];
    float* out = (float*)d_out;

    float* fbuf = nullptr;
    cudaGetSymbolAddress((void**)&fbuf, g_fbuf);
    float* h0 = fbuf + OFF_H0;
    float* x1 = fbuf + OFF_X1;
    float* x2 = fbuf + OFF_X2;
    float* x3 = fbuf + OFF_X3;
    float* x4 = fbuf + OFF_X4;
    float* h5 = fbuf + OFF_H5;
    float* h6 = fbuf + OFF_H6;
    float* h7 = fbuf + OFF_H7;

    // normalization + CSR build
    k_init_stats<<<1, 1>>>();
    k_zero_deg<<<NBLK_N, 256>>>();
    k_stats<<<NBLK_N, 256>>>(x);
    k_normalize<<<NBLK_N, 256>>>(x, h0);
    k_count<<<NBLK_E, 256>>>(dst);
    k_scan1<<<NBLK_N, 256>>>();
    k_scan2<<<1, 1>>>();
    k_scan3<<<NBLK_N, 256>>>();
    k_scatter<<<NBLK_E, 256>>>(src, dst);

    // 7 SAGE layers
    {
        constexpr int NB = 256 / 3;
        k_sage<3, 8, false><<<(N_NODES + NB - 1) / NB, 256>>>(h0, nullptr, x1, cw[0][0], cw[0][1], cw[0][2]);
    }
    {
        constexpr int NB = 256 / 8;
        k_sage<8, 16, false><<<(N_NODES + NB - 1) / NB, 256>>>(x1, nullptr, x2, cw[1][0], cw[1][1], cw[1][2]);
    }
    {
        constexpr int NB = 256 / 16;
        k_sage<16, 32, false><<<(N_NODES + NB - 1) / NB, 256>>>(x2, nullptr, x3, cw[2][0], cw[2][1], cw[2][2]);
    }
    {
        constexpr int NB = 256 / 32;
        k_sage<32, 64, false><<<(N_NODES + NB - 1) / NB, 256>>>(x3, nullptr, x4, cw[3][0], cw[3][1], cw[3][2]);
    }
    {
        constexpr int NB = 256 / 64;
        k_sage<64, 32, true><<<(N_NODES + NB - 1) / NB, 256>>>(x4, x3, h5, cw[4][0], cw[4][1], cw[4][2]);
    }
    {
        constexpr int NB = 256 / 32;
        k_sage<32, 16, true><<<(N_NODES + NB - 1) / NB, 256>>>(h5, x2, h6, cw[5][0], cw[5][1], cw[5][2]);
    }
    {
        constexpr int NB = 256 / 16;
        k_sage<16, 8, true><<<(N_NODES + NB - 1) / NB, 256>>>(h6, x1, h7, cw[6][0], cw[6][1], cw[6][2]);
    }

    // MLP head + softmax
    k_mlp<<<NBLK_N, 256>>>(h7, lin1_w, lin1_b, lin2_w, lin2_b, lin3_w, lin3_b, out);
}

// round 2
// speedup vs baseline: 1.1444x; 1.1444x over previous
#include <cuda_runtime.h>
#include <math.h>

#define N_NODES 100000
#define N_EDGES 3200000
#define NBLK_N 391            // ceil(100000/256)
#define NBLK_E 12500          // 3200000/256

typedef unsigned long long u64;

// ---------------- static device scratch (allocation-free) ----------------
static __device__ float g_h0[400000];      // padded stride 4
static __device__ float g_x1[800000];
static __device__ float g_x2[1600000];
static __device__ float g_x3[3200000];
static __device__ float g_x4[6400000];
static __device__ float g_h5[3200000];
static __device__ float g_h6[1600000];
static __device__ float g_h7[800000];
static __device__ float g_y[3200000];      // pre-transformed gather source

static __device__ int   g_deg[N_NODES];
static __device__ int   g_row[N_NODES];
static __device__ int   g_cur[N_NODES];
static __device__ int   g_part[512];
static __device__ int   g_srcs[N_EDGES];
static __device__ float g_invdeg[N_NODES];

// normalization stats (ordered-uint encoding for max/min)
static __device__ unsigned g_maxx, g_minx, g_maxy, g_miny, g_maxrx, g_maxry, g_maxa;
static __device__ float g_sumx, g_sumy;

// ---------------- helpers ----------------
__device__ __forceinline__ unsigned f2o(float f) {
    unsigned u = __float_as_uint(f);
    return (u & 0x80000000u) ? ~u : (u | 0x80000000u);
}
__device__ __forceinline__ float o2f(unsigned u) {
    return (u & 0x80000000u) ? __uint_as_float(u & 0x7FFFFFFFu) : __uint_as_float(~u);
}

__device__ __forceinline__ u64 pack2(float a, float b) {
    u64 r; asm("mov.b64 %0,{%1,%2};" : "=l"(r) : "f"(a), "f"(b)); return r;
}
__device__ __forceinline__ void unpack2(u64 v, float& a, float& b) {
    asm("mov.b64 {%0,%1},%2;" : "=f"(a), "=f"(b) : "l"(v));
}
__device__ __forceinline__ u64 fma2(u64 a, u64 b, u64 c) {
    u64 d; asm("fma.rn.f32x2 %0,%1,%2,%3;" : "=l"(d) : "l"(a), "l"(b), "l"(c)); return d;
}

__device__ __forceinline__ float blockSum(float v, float* s) {
    int t = threadIdx.x;
    s[t] = v; __syncthreads();
    for (int o = 128; o > 0; o >>= 1) { if (t < o) s[t] += s[t + o]; __syncthreads(); }
    float r = s[0]; __syncthreads();
    return r;
}
__device__ __forceinline__ float blockMax(float v, float* s) {
    int t = threadIdx.x;
    s[t] = v; __syncthreads();
    for (int o = 128; o > 0; o >>= 1) { if (t < o) s[t] = fmaxf(s[t], s[t + o]); __syncthreads(); }
    float r = s[0]; __syncthreads();
    return r;
}
__device__ __forceinline__ float blockMin(float v, float* s) {
    int t = threadIdx.x;
    s[t] = v; __syncthreads();
    for (int o = 128; o > 0; o >>= 1) { if (t < o) s[t] = fminf(s[t], s[t + o]); __syncthreads(); }
    float r = s[0]; __syncthreads();
    return r;
}

// ---------------- setup kernels ----------------
__global__ void k_init_stats() {
    g_maxx = 0u; g_maxy = 0u; g_maxrx = 0u; g_maxry = 0u; g_maxa = 0u;
    g_minx = 0xFFFFFFFFu; g_miny = 0xFFFFFFFFu;
    g_sumx = 0.f; g_sumy = 0.f;
}

__global__ void k_zero_deg() {
    int i = blockIdx.x * blockDim.x + threadIdx.x;
    if (i < N_NODES) g_deg[i] = 0;
}

__global__ void __launch_bounds__(256) k_stats(const float* __restrict__ x) {
    __shared__ float s[256];
    int n = blockIdx.x * 256 + threadIdx.x;
    float X = -3.402823466e38f, Y = -3.402823466e38f, A = -3.402823466e38f;
    float Xm = 3.402823466e38f, Ym = 3.402823466e38f;
    float sx = 0.f, sy = 0.f, RX = -3.402823466e38f, RY = -3.402823466e38f;
    const float th = (float)(M_PI / 2.0);
    const float c = cosf(th), sn = sinf(th);
    if (n < N_NODES) {
        float px = x[n * 3 + 0], py = x[n * 3 + 1], pa = x[n * 3 + 2];
        X = px; Xm = px; Y = py; Ym = py; A = pa;
        sx = px; sy = py;
        RX = c * px - sn * py;
        RY = sn * px + c * py;
    }
    float bs;
    bs = blockMax(X, s);  if (threadIdx.x == 0) atomicMax(&g_maxx, f2o(bs));
    bs = blockMin(Xm, s); if (threadIdx.x == 0) atomicMin(&g_minx, f2o(bs));
    bs = blockMax(Y, s);  if (threadIdx.x == 0) atomicMax(&g_maxy, f2o(bs));
    bs = blockMin(Ym, s); if (threadIdx.x == 0) atomicMin(&g_miny, f2o(bs));
    bs = blockMax(RX, s); if (threadIdx.x == 0) atomicMax(&g_maxrx, f2o(bs));
    bs = blockMax(RY, s); if (threadIdx.x == 0) atomicMax(&g_maxry, f2o(bs));
    bs = blockMax(A, s);  if (threadIdx.x == 0) atomicMax(&g_maxa, f2o(bs));
    bs = blockSum(sx, s); if (threadIdx.x == 0) atomicAdd(&g_sumx, bs);
    bs = blockSum(sy, s); if (threadIdx.x == 0) atomicAdd(&g_sumy, bs);
}

__global__ void __launch_bounds__(256) k_normalize(const float* __restrict__ x) {
    int n = blockIdx.x * 256 + threadIdx.x;
    if (n >= N_NODES) return;
    float maxx = o2f(g_maxx), minx = o2f(g_minx);
    float maxy = o2f(g_maxy), miny = o2f(g_miny);
    float maxa = o2f(g_maxa);
    float meanx = g_sumx / (float)N_NODES, meany = g_sumy / (float)N_NODES;
    bool cond = (maxy - miny) > (maxx - minx);
    const float th = (float)(M_PI / 2.0);
    const float c = cosf(th), sn = sinf(th);
    float px = x[n * 3 + 0], py = x[n * 3 + 1], pa = x[n * 3 + 2];
    float cx, cy, mnx, mny, mxx, mxy;
    if (cond) {
        cx = c * px - sn * py;
        cy = sn * px + c * py;
        mnx = c * meanx - sn * meany;
        mny = sn * meanx + c * meany;
        mxx = o2f(g_maxrx);
        mxy = o2f(g_maxry);
    } else {
        cx = px; cy = py; mnx = meanx; mny = meany; mxx = maxx; mxy = maxy;
    }
    float4 o;
    o.x = (cx - mnx) / mxx;
    o.y = (cy - mny) / mxy;
    o.z = pa / maxa;
    o.w = 0.f;
    ((float4*)g_h0)[n] = o;
}

// ---------------- CSR build ----------------
__global__ void k_count(const int* __restrict__ dst) {
    int e = blockIdx.x * blockDim.x + threadIdx.x;
    if (e < N_EDGES) atomicAdd(&g_deg[dst[e]], 1);
}

__global__ void __launch_bounds__(256) k_scan1() {
    __shared__ int s[256];
    int t = threadIdx.x;
    int i = blockIdx.x * 256 + t;
    s[t] = (i < N_NODES) ? g_deg[i] : 0;
    __syncthreads();
    for (int o = 128; o > 0; o >>= 1) { if (t < o) s[t] += s[t + o]; __syncthreads(); }
    if (t == 0) g_part[blockIdx.x] = s[0];
}

// parallel scan of the 391 block partials (one block, 512 threads)
__global__ void __launch_bounds__(512) k_scan2() {
    __shared__ int s[512];
    int t = threadIdx.x;
    int v = (t < NBLK_N) ? g_part[t] : 0;
    s[t] = v; __syncthreads();
    for (int o = 1; o < 512; o <<= 1) {
        int a = (t >= o) ? s[t - o] : 0;
        __syncthreads();
        s[t] += a;
        __syncthreads();
    }
    if (t < NBLK_N) g_part[t] = s[t] - v;  // exclusive prefix
}

__global__ void __launch_bounds__(256) k_scan3() {
    __shared__ int s[256];
    int t = threadIdx.x;
    int i = blockIdx.x * 256 + t;
    int v = (i < N_NODES) ? g_deg[i] : 0;
    s[t] = v; __syncthreads();
    for (int o = 1; o < 256; o <<= 1) {
        int a = (t >= o) ? s[t - o] : 0;
        __syncthreads();
        s[t] += a;
        __syncthreads();
    }
    if (i < N_NODES) {
        int ex = g_part[blockIdx.x] + s[t] - v;
        g_row[i] = ex;
        g_cur[i] = ex;
        g_invdeg[i] = 1.0f / (float)(v > 0 ? v : 1);
    }
}

__global__ void k_scatter(const int* __restrict__ src, const int* __restrict__ dst) {
    int e = blockIdx.x * blockDim.x + threadIdx.x;
    if (e < N_EDGES) {
        int pos = atomicAdd(&g_cur[dst[e]], 1);
        g_srcs[pos] = src[e];
    }
}

// ---------------- pre-transform: y = x @ wl (for FO < FI layers) ----------------
template <int FI, int FO>
__global__ void __launch_bounds__(256) k_xform(const float* __restrict__ xin,
                                               float* __restrict__ y,
                                               const float* __restrict__ wl) {
    __shared__ __align__(16) float s_w[FI * FO];
    int t = threadIdx.x;
    for (int i = t; i < FI * FO; i += 256) s_w[i] = wl[i];
    __syncthreads();
    int n = blockIdx.x * 256 + t;
    if (n >= N_NODES) return;
    float xr[FI];
#pragma unroll
    for (int i = 0; i < FI; i++) xr[i] = xin[(size_t)n * FI + i];
#pragma unroll
    for (int f2 = 0; f2 < FO / 2; f2++) {
        u64 v = pack2(0.f, 0.f);
#pragma unroll
        for (int i = 0; i < FI; i++) {
            u64 x2 = pack2(xr[i], xr[i]);
            v = fma2(x2, ((const u64*)s_w)[i * (FO / 2) + f2], v);
        }
        float a, b; unpack2(v, a, b);
        ((float2*)y)[(size_t)n * (FO / 2) + f2] = make_float2(a, b);
    }
}

// ---------------- fused SAGE layer ----------------
// GD  = floats gathered per row (multiple of 4); gsrc rows have stride GD floats
// FI  = input feature dim for x@wr ; FIS = stride of xin rows (floats)
// FO  = output dim ; RES = add residual ; PRE = gsrc is pre-transformed (mean@wl done)
template <int GD, int FI, int FIS, int FO, bool RES, bool PRE>
__global__ void __launch_bounds__(256) k_sage(const float4* __restrict__ gsrc,
                                              const float* __restrict__ xin,
                                              const float* __restrict__ res,
                                              float* __restrict__ xout,
                                              const float* __restrict__ wl,
                                              const float* __restrict__ bl,
                                              const float* __restrict__ wr) {
    constexpr int TPN = GD / 4;        // threads per node (phase 1)
    constexpr int NB = 256 / TPN;      // nodes per block
    constexpr int WLSZ = PRE ? 2 : FI * FO;
    __shared__ __align__(16) float s_mean[NB * GD];
    __shared__ __align__(16) float s_wl[WLSZ];
    __shared__ __align__(16) float s_wr[FI * FO];
    __shared__ float s_bl[FO];
    int t = threadIdx.x;
    if (!PRE) for (int i = t; i < FI * FO; i += 256) s_wl[i] = wl[i];
    for (int i = t; i < FI * FO; i += 256) s_wr[i] = wr[i];
    if (t < FO) s_bl[t] = bl[t];

    int nbase = blockIdx.x * NB;

    // phase 1: mean aggregation via CSR gather (float4, 4-edge unroll)
    {
        int nl = t / TPN, q = t % TPN;
        int n = nbase + nl;
        float4 r = make_float4(0.f, 0.f, 0.f, 0.f);
        if (n < N_NODES) {
            int start = g_row[n];
            int dg = g_deg[n];
            const int* sp = g_srcs + start;
            float4 a0 = r, a1 = r, a2 = r, a3 = r;
            int e = 0;
            for (; e + 4 <= dg; e += 4) {
                int s0 = sp[e], s1 = sp[e + 1], s2 = sp[e + 2], s3 = sp[e + 3];
                float4 v0 = gsrc[(size_t)s0 * TPN + q];
                float4 v1 = gsrc[(size_t)s1 * TPN + q];
                float4 v2 = gsrc[(size_t)s2 * TPN + q];
                float4 v3 = gsrc[(size_t)s3 * TPN + q];
                a0.x += v0.x; a0.y += v0.y; a0.z += v0.z; a0.w += v0.w;
                a1.x += v1.x; a1.y += v1.y; a1.z += v1.z; a1.w += v1.w;
                a2.x += v2.x; a2.y += v2.y; a2.z += v2.z; a2.w += v2.w;
                a3.x += v3.x; a3.y += v3.y; a3.z += v3.z; a3.w += v3.w;
            }
            for (; e < dg; e++) {
                float4 v = gsrc[(size_t)sp[e] * TPN + q];
                a0.x += v.x; a0.y += v.y; a0.z += v.z; a0.w += v.w;
            }
            float inv = g_invdeg[n];
            r.x = ((a0.x + a1.x) + (a2.x + a3.x)) * inv;
            r.y = ((a0.y + a1.y) + (a2.y + a3.y)) * inv;
            r.z = ((a0.z + a1.z) + (a2.z + a3.z)) * inv;
            r.w = ((a0.w + a1.w) + (a2.w + a3.w)) * inv;
        }
        ((float4*)s_mean)[nl * TPN + q] = r;
    }
    __syncthreads();

    // phase 2: out = tanh(mean@wl + bl + x@wr) [+ res], packed f32x2 over fo pairs
    constexpr int PAIRS = FO / 2;
    constexpr int NP2 = 256 / PAIRS;
    for (int p = 0; p < NB; p += NP2) {
        int nl2 = p + t / PAIRS;
        int fo2 = t % PAIRS;
        if (nl2 < NB) {
            int n = nbase + nl2;
            if (n < N_NODES) {
                float b0 = s_bl[2 * fo2], b1 = s_bl[2 * fo2 + 1];
                if (PRE) { b0 += s_mean[nl2 * GD + 2 * fo2]; b1 += s_mean[nl2 * GD + 2 * fo2 + 1]; }
                u64 v = pack2(b0, b1);
                const float* xr = xin + (size_t)n * FIS;
#pragma unroll
                for (int i = 0; i < FI; i++) {
                    float xi = xr[i];
                    u64 xv = pack2(xi, xi);
                    v = fma2(xv, ((const u64*)s_wr)[i * PAIRS + fo2], v);
                    if (!PRE) {
                        float mi = s_mean[nl2 * GD + i];
                        u64 mv = pack2(mi, mi);
                        v = fma2(mv, ((const u64*)s_wl)[i * PAIRS + fo2], v);
                    }
                }
                float r0, r1; unpack2(v, r0, r1);
                r0 = tanhf(r0); r1 = tanhf(r1);
                if (RES) {
                    float2 rr = ((const float2*)res)[(size_t)n * PAIRS + fo2];
                    r0 += rr.x; r1 += rr.y;
                }
                ((float2*)xout)[(size_t)n * PAIRS + fo2] = make_float2(r0, r1);
            }
        }
    }
}

// ---------------- MLP head + softmax ----------------
__global__ void __launch_bounds__(256) k_mlp(const float* __restrict__ h,
                                             const float* __restrict__ w1, const float* __restrict__ b1,
                                             const float* __restrict__ w2, const float* __restrict__ b2,
                                             const float* __restrict__ w3, const float* __restrict__ b3,
                                             float* __restrict__ out) {
    __shared__ float s1[8 * 32], sb1[32], s2[32 * 16], sb2[16], s3[16 * 2], sb3[2];
    int t = threadIdx.x;
    for (int i = t; i < 256; i += 256) s1[i] = w1[i];
    for (int i = t; i < 512; i += 256) s2[i] = w2[i];
    if (t < 32) { sb1[t] = b1[t]; s3[t] = w3[t]; }
    if (t < 16) sb2[t] = b2[t];
    if (t < 2) sb3[t] = b3[t];
    __syncthreads();
    int n = blockIdx.x * 256 + t;
    if (n >= N_NODES) return;
    float in8[8];
#pragma unroll
    for (int i = 0; i < 8; i++) in8[i] = h[n * 8 + i];
    float a[32];
#pragma unroll
    for (int j = 0; j < 32; j++) {
        float v = sb1[j];
#pragma unroll
        for (int i = 0; i < 8; i++) v += in8[i] * s1[i * 32 + j];
        a[j] = tanhf(v);
    }
    float bb[16];
#pragma unroll
    for (int j = 0; j < 16; j++) {
        float v = sb2[j];
#pragma unroll
        for (int i = 0; i < 32; i++) v += a[i] * s2[i * 16 + j];
        bb[j] = tanhf(v);
    }
    float c0 = sb3[0], c1 = sb3[1];
#pragma unroll
    for (int i = 0; i < 16; i++) { c0 += bb[i] * s3[i * 2 + 0]; c1 += bb[i] * s3[i * 2 + 1]; }
    float m = fmaxf(c0, c1);
    float e0 = expf(c0 - m), e1 = expf(c1 - m);
    float inv = 1.f / (e0 + e1);
    out[n * 2 + 0] = e0 * inv;
    out[n * 2 + 1] = e1 * inv;
}

// ---------------- launch ----------------
extern "C" void kernel_launch(void* const* d_in, const int* in_sizes, int n_in,
                              void* d_out, int out_size) {
    const float* x = (const float*)d_in[0];
    const int* ei = (const int*)d_in[1];
    const int* src = ei;
    const int* dst = ei + N_EDGES;

    const float* cw[7][3];
    for (int l = 0; l < 7; l++) {
        cw[l][0] = (const float*)d_in[2 + 3 * l + 0];
        cw[l][1] = (const float*)d_in[2 + 3 * l + 1];
        cw[l][2] = (const float*)d_in[2 + 3 * l + 2];
    }
    const float* lin1_w = (const float*)d_in[23];
    const float* lin1_b = (const float*)d_in[24];
    const float* lin2_w = (const float*)d_in[25];
    const float* lin2_b = (const float*)d_in[26];
    const float* lin3_w = (const float*)d_in[27];
    const float* lin3_b = (const float*)d_in[28];
    float* out = (float*)d_out;

    float *h0, *x1, *x2, *x3, *x4, *h5, *h6, *h7, *yb;
    cudaGetSymbolAddress((void**)&h0, g_h0);
    cudaGetSymbolAddress((void**)&x1, g_x1);
    cudaGetSymbolAddress((void**)&x2, g_x2);
    cudaGetSymbolAddress((void**)&x3, g_x3);
    cudaGetSymbolAddress((void**)&x4, g_x4);
    cudaGetSymbolAddress((void**)&h5, g_h5);
    cudaGetSymbolAddress((void**)&h6, g_h6);
    cudaGetSymbolAddress((void**)&h7, g_h7);
    cudaGetSymbolAddress((void**)&yb, g_y);

    // normalization + CSR build
    k_init_stats<<<1, 1>>>();
    k_zero_deg<<<NBLK_N, 256>>>();
    k_stats<<<NBLK_N, 256>>>(x);
    k_normalize<<<NBLK_N, 256>>>(x);
    k_count<<<NBLK_E, 256>>>(dst);
    k_scan1<<<NBLK_N, 256>>>();
    k_scan2<<<1, 512>>>();
    k_scan3<<<NBLK_N, 256>>>();
    k_scatter<<<NBLK_E, 256>>>(src, dst);

    // L1: 3->8 (h0 padded stride 4), gather x (GD=4)
    k_sage<4, 3, 4, 8, false, false><<<(N_NODES + 255) / 256, 256>>>(
        (const float4*)h0, h0, nullptr, x1, cw[0][0], cw[0][1], cw[0][2]);
    // L2: 8->16, gather x (GD=8)
    k_sage<8, 8, 8, 16, false, false><<<(N_NODES + 127) / 128, 256>>>(
        (const float4*)x1, x1, nullptr, x2, cw[1][0], cw[1][1], cw[1][2]);
    // L3: 16->32, gather x (GD=16)
    k_sage<16, 16, 16, 32, false, false><<<(N_NODES + 63) / 64, 256>>>(
        (const float4*)x2, x2, nullptr, x3, cw[2][0], cw[2][1], cw[2][2]);
    // L4: 32->64, gather x (GD=32)
    k_sage<32, 32, 32, 64, false, false><<<(N_NODES + 31) / 32, 256>>>(
        (const float4*)x3, x3, nullptr, x4, cw[3][0], cw[3][1], cw[3][2]);
    // L5: 64->32, PRE: y = x4 @ wl, gather y (GD=32)
    k_xform<64, 32><<<NBLK_N, 256>>>(x4, yb, cw[4][0]);
    k_sage<32, 64, 64, 32, true, true><<<(N_NODES + 31) / 32, 256>>>(
        (const float4*)yb, x4, x3, h5, cw[4][0], cw[4][1], cw[4][2]);
    // L6: 32->16, PRE
    k_xform<32, 16><<<NBLK_N, 256>>>(h5, yb, cw[5][0]);
    k_sage<16, 32, 32, 16, true, true><<<(N_NODES + 63) / 64, 256>>>(
        (const float4*)yb, h5, x2, h6, cw[5][0], cw[5][1], cw[5][2]);
    // L7: 16->8, PRE
    k_xform<16, 8><<<NBLK_N, 256>>>(h6, yb, cw[6][0]);
    k_sage<8, 16, 16, 8, true, true><<<(N_NODES + 127) / 128, 256>>>(
        (const float4*)yb, h6, x1, h7, cw[6][0], cw[6][1], cw[6][2]);

    // MLP head + softmax
    k_mlp<<<NBLK_N, 256>>>(h7, lin1_w, lin1_b, lin2_w, lin2_b, lin3_w, lin3_b, out);
}